// round 10
// baseline (speedup 1.0000x reference)
#include <cuda_runtime.h>
#include <cuda_fp16.h>
#include <cstdint>

#define Bn 32
#define Cn 256
#define Tn 4096

// Static device scratch (allocation-guard legal).
__device__ float4   g_e4[(size_t)Bn * Cn * Cn / 4];      //  8 MB energy (fp32)
__device__ uint32_t g_ah32[(size_t)Bn * Cn * Cn / 2];    //  4 MB attn hi (f16)
__device__ uint32_t g_al32[(size_t)Bn * Cn * Cn / 2];    //  4 MB attn lo (f16)
__device__ uint32_t g_xth32[(size_t)Bn * Tn * Cn / 2];   // 67 MB X^T hi (f16)

// ---------------------------------------------------------------------------
// Tile layout: row = 64 k f16 = 128 B = 32 words; group g (16 B = 4 k-pairs)
// at word offset row*32 + (g^(row&7))*4. LDSM/STS.128/cp.async conflict-free.
// ---------------------------------------------------------------------------
__device__ __forceinline__ int woff(int row, int g) {
    return row * 32 + ((g ^ (row & 7)) << 2);
}
__device__ __forceinline__ uint32_t smem_u32(const void* p) {
    uint32_t a;
    asm("{ .reg .u64 t; cvta.to.shared.u64 t, %1; cvt.u32.u64 %0, t; }"
        : "=r"(a) : "l"(p));
    return a;
}
__device__ __forceinline__ uint32_t packh2(__half a, __half b) {
    return (uint32_t)__half_as_ushort(a) | ((uint32_t)__half_as_ushort(b) << 16);
}
__device__ __forceinline__ void mma_f16(float* d, const uint32_t* a, const uint32_t* b) {
    asm volatile(
        "mma.sync.aligned.m16n8k16.row.col.f32.f16.f16.f32 "
        "{%0,%1,%2,%3}, {%4,%5,%6,%7}, {%8,%9}, {%0,%1,%2,%3};"
        : "+f"(d[0]), "+f"(d[1]), "+f"(d[2]), "+f"(d[3])
        : "r"(a[0]), "r"(a[1]), "r"(a[2]), "r"(a[3]), "r"(b[0]), "r"(b[1]));
}
__device__ __forceinline__ void ldsm4(uint32_t& r0, uint32_t& r1, uint32_t& r2,
                                      uint32_t& r3, uint32_t addr) {
    asm volatile("ldmatrix.sync.aligned.m8n8.x4.shared.b16 {%0,%1,%2,%3}, [%4];"
                 : "=r"(r0), "=r"(r1), "=r"(r2), "=r"(r3) : "r"(addr));
}
// A fragment (m16 x k16) at (mrow, ks): octets -> (rows 0-7/8-15) x (k lo/hi).
__device__ __forceinline__ void lda_frag(uint32_t* a, uint32_t tb, int mrow,
                                         int ks, int lane) {
    int oct = lane >> 3, l7 = lane & 7;
    int row = mrow + ((oct & 1) << 3) + l7;
    int g = 2 * ks + (oct >> 1);
    ldsm4(a[0], a[1], a[2], a[3], tb + 4 * woff(row, g));
}
// B fragments for TWO n8-atoms (n16 x k16): {b0(na), b1(na), b0(na+1), b1(na+1)}.
__device__ __forceinline__ void ldb_frag(uint32_t* b, uint32_t tb, int nrow,
                                         int ks, int lane) {
    int oct = lane >> 3, l7 = lane & 7;
    int row = nrow + ((oct >> 1) << 3) + l7;
    int g = 2 * ks + (oct & 1);
    ldsm4(b[0], b[1], b[2], b[3], tb + 4 * woff(row, g));
}
// cp.async (sm_80 baseline feature; 16B, L1-bypass).
__device__ __forceinline__ void cp16(uint32_t saddr, const void* g) {
    asm volatile("cp.async.cg.shared.global [%0], [%1], 16;" :: "r"(saddr), "l"(g));
}
#define CP_COMMIT() asm volatile("cp.async.commit_group;" ::: "memory")
#define CP_WAIT(N)  asm volatile("cp.async.wait_group %0;" :: "n"(N) : "memory")

__device__ __forceinline__ void splitpack(float4 u, float4 v, uint4& H, uint4& L) {
    __half h0 = __float2half_rn(u.x), h1 = __float2half_rn(u.y);
    __half h2 = __float2half_rn(u.z), h3 = __float2half_rn(u.w);
    __half h4 = __float2half_rn(v.x), h5 = __float2half_rn(v.y);
    __half h6 = __float2half_rn(v.z), h7 = __float2half_rn(v.w);
    H = make_uint4(packh2(h0, h1), packh2(h2, h3), packh2(h4, h5), packh2(h6, h7));
    L = make_uint4(
        packh2(__float2half_rn(u.x - __half2float(h0)), __float2half_rn(u.y - __half2float(h1))),
        packh2(__float2half_rn(u.z - __half2float(h2)), __float2half_rn(u.w - __half2float(h3))),
        packh2(__float2half_rn(v.x - __half2float(h4)), __float2half_rn(v.y - __half2float(h5))),
        packh2(__float2half_rn(v.z - __half2float(h6)), __float2half_rn(v.w - __half2float(h7))));
}

// ---------------------------------------------------------------------------
// Transpose + f16-round: xt_h[b][t][c] = f16(x[b][c][t])
// ---------------------------------------------------------------------------
__global__ __launch_bounds__(256) void transpose_h(const float* __restrict__ x) {
    __shared__ float tile[32][33];
    const int b = blockIdx.z, c0 = blockIdx.y * 32, t0 = blockIdx.x * 32;
    const int tx = threadIdx.x, ty = threadIdx.y;
    const float* Xb = x + ((size_t)b * Cn + c0) * Tn + t0;
    __half* Xt = (__half*)g_xth32 + ((size_t)b * Tn + t0) * Cn + c0;
#pragma unroll
    for (int r = 0; r < 32; r += 8) tile[ty + r][tx] = Xb[(size_t)(ty + r) * Tn + tx];
    __syncthreads();
#pragma unroll
    for (int r = 0; r < 32; r += 8)
        Xt[(size_t)(ty + r) * Cn + tx] = __float2half_rn(tile[tx][ty + r]);
}

// ---------------------------------------------------------------------------
// GEMM1: E[b] = X[b]*X[b]^T, 3xFP16. CTA 128x128, 8 warps (64x32 tiles), BK=64.
// Stage words: AH 0, AL 4096, BH 8192, BL 12288; stage stride 16384 (128 KB).
// ---------------------------------------------------------------------------
__device__ __forceinline__ void g1_chunk(uint32_t sbase, float acc[16][4],
                                         int warpM, int warpN, int lane) {
    const uint32_t AH = sbase, AL = sbase + 4096 * 4;
    const uint32_t BH = sbase + 8192 * 4, BL = sbase + 12288 * 4;
#pragma unroll
    for (int ks = 0; ks < 4; ks++) {
        uint32_t ah[4][4], al[4][4], bh[4][2], bl[4][2];
#pragma unroll
        for (int ma = 0; ma < 4; ma++) lda_frag(ah[ma], AH, warpM + ma * 16, ks, lane);
#pragma unroll
        for (int ma = 0; ma < 4; ma++) lda_frag(al[ma], AL, warpM + ma * 16, ks, lane);
        ldb_frag(&bh[0][0], BH, warpN, ks, lane);
        ldb_frag(&bh[2][0], BH, warpN + 16, ks, lane);
        ldb_frag(&bl[0][0], BL, warpN, ks, lane);
        ldb_frag(&bl[2][0], BL, warpN + 16, ks, lane);
#pragma unroll
        for (int ma = 0; ma < 4; ma++)
#pragma unroll
            for (int na = 0; na < 4; na++) {
                float* d = acc[ma * 4 + na];
                mma_f16(d, ah[ma], bh[na]);
                mma_f16(d, al[ma], bh[na]);
                mma_f16(d, ah[ma], bl[na]);
            }
    }
}

__global__ __launch_bounds__(256, 1) void gemm1_h(const float* __restrict__ x) {
    extern __shared__ uint32_t sm[];
    const uint32_t sb = smem_u32(sm);
    const int tid = threadIdx.x, lane = tid & 31, wid = tid >> 5;
    const int gid = lane >> 2, tig = lane & 3;
    const int warpM = (wid >> 2) * 64, warpN = (wid & 3) * 32;
    const float* Xb = x + (size_t)blockIdx.z * Cn * Tn;
    const float* Ag = Xb + (size_t)blockIdx.y * 128 * Tn;
    const float* Bg = Xb + (size_t)blockIdx.x * 128 * Tn;

    const int frow = tid >> 3, fg = tid & 7;   // fetch map: 4 its x (row, g)

    float acc[16][4];
#pragma unroll
    for (int a = 0; a < 16; a++)
#pragma unroll
        for (int c = 0; c < 4; c++) acc[a][c] = 0.f;

    float4 va[8], vb[8];
    auto fetch = [&](int c) {
#pragma unroll
        for (int it = 0; it < 4; it++) {
            int row = frow + it * 32;
            const float* pa = Ag + (size_t)row * Tn + c * 64 + fg * 8;
            const float* pb = Bg + (size_t)row * Tn + c * 64 + fg * 8;
            va[2 * it] = *(const float4*)pa;     va[2 * it + 1] = *(const float4*)(pa + 4);
            vb[2 * it] = *(const float4*)pb;     vb[2 * it + 1] = *(const float4*)(pb + 4);
        }
    };
    auto stage = [&](int s) {
        uint32_t* st = sm + s * 16384;
#pragma unroll
        for (int it = 0; it < 4; it++) {
            int row = frow + it * 32;
            int w = woff(row, fg);
            uint4 H, L;
            splitpack(va[2 * it], va[2 * it + 1], H, L);
            *(uint4*)(st + w) = H;
            *(uint4*)(st + 4096 + w) = L;
            splitpack(vb[2 * it], vb[2 * it + 1], H, L);
            *(uint4*)(st + 8192 + w) = H;
            *(uint4*)(st + 12288 + w) = L;
        }
    };

    fetch(0);
    stage(0);
    __syncthreads();

    const int NC = Tn / 64;
#pragma unroll 1
    for (int c = 0; c < NC; c++) {
        const int s = c & 1;
        if (c + 1 < NC) fetch(c + 1);
        g1_chunk(sb + s * 16384 * 4, acc, warpM, warpN, lane);
        if (c + 1 < NC) {
            stage(s ^ 1);
            __syncthreads();
        }
    }

    float* E = (float*)g_e4 + (size_t)blockIdx.z * Cn * Cn;
#pragma unroll
    for (int ma = 0; ma < 4; ma++)
#pragma unroll
        for (int na = 0; na < 4; na++) {
            const float* d = acc[ma * 4 + na];
            int r0 = blockIdx.y * 128 + warpM + ma * 16 + gid;
            int cc = blockIdx.x * 128 + warpN + na * 8 + 2 * tig;
            *(float2*)(E + (size_t)r0 * Cn + cc) = make_float2(d[0], d[1]);
            *(float2*)(E + (size_t)(r0 + 8) * Cn + cc) = make_float2(d[2], d[3]);
        }
}

// ---------------------------------------------------------------------------
// Softmax: w = exp(min_e - e)/sum (== softmax(rowmax - e)); writes f16 h+l.
// ---------------------------------------------------------------------------
__global__ __launch_bounds__(256) void softmax_kernel() {
    const int row = blockIdx.x;
    const float* E = (float*)g_e4 + (size_t)row * Cn;
    const int tid = threadIdx.x;

    float e = E[tid];
    float v = e;
#pragma unroll
    for (int o = 16; o; o >>= 1) v = fminf(v, __shfl_xor_sync(0xffffffffu, v, o));
    __shared__ float red[8];
    __shared__ float bc[2];
    if ((tid & 31) == 0) red[tid >> 5] = v;
    __syncthreads();
    if (tid == 0) {
        float m = red[0];
#pragma unroll
        for (int i = 1; i < 8; i++) m = fminf(m, red[i]);
        bc[0] = m;
    }
    __syncthreads();
    float p = expf(bc[0] - e);
    v = p;
#pragma unroll
    for (int o = 16; o; o >>= 1) v += __shfl_xor_sync(0xffffffffu, v, o);
    if ((tid & 31) == 0) red[tid >> 5] = v;
    __syncthreads();
    if (tid == 0) {
        float s = 0.f;
#pragma unroll
        for (int i = 0; i < 8; i++) s += red[i];
        bc[1] = 1.0f / s;
    }
    __syncthreads();
    float w = p * bc[1];
    __half h = __float2half_rn(w);
    ((__half*)g_ah32)[(size_t)row * Cn + tid] = h;
    ((__half*)g_al32)[(size_t)row * Cn + tid] =
        __float2half_rn(w - __half2float(h));
}

// ---------------------------------------------------------------------------
// GEMM2: out = gamma*(Attn*X) + X. CTA 128x256, 8 warps (64x64 tiles), BK=64.
// All operands pre-split f16 -> cp.async 2-stage pipeline.
// Stage words: AH 0, AL 4096, BH 8192..16383; stride 16384 (128 KB total).
// ---------------------------------------------------------------------------
__device__ __forceinline__ void g2_chunk(uint32_t sbase, float acc[32][4],
                                         int warpM, int warpN, int lane) {
    const uint32_t AH = sbase, AL = sbase + 4096 * 4, BH = sbase + 8192 * 4;
#pragma unroll
    for (int ks = 0; ks < 4; ks++) {
        uint32_t ah[4][4], al[4][4], bh[8][2];
#pragma unroll
        for (int ma = 0; ma < 4; ma++) lda_frag(ah[ma], AH, warpM + ma * 16, ks, lane);
#pragma unroll
        for (int ma = 0; ma < 4; ma++) lda_frag(al[ma], AL, warpM + ma * 16, ks, lane);
#pragma unroll
        for (int p = 0; p < 4; p++) ldb_frag(&bh[2 * p][0], BH, warpN + p * 16, ks, lane);
#pragma unroll
        for (int ma = 0; ma < 4; ma++)
#pragma unroll
            for (int na = 0; na < 8; na++) {
                float* d = acc[ma * 8 + na];
                mma_f16(d, ah[ma], bh[na]);
                mma_f16(d, al[ma], bh[na]);
            }
    }
}

__global__ __launch_bounds__(256, 1) void gemm2_h(const float* __restrict__ x,
                                                  const float* __restrict__ gamma,
                                                  float* __restrict__ out) {
    extern __shared__ uint32_t sm[];
    const uint32_t sb = smem_u32(sm);
    const int tid = threadIdx.x, lane = tid & 31, wid = tid >> 5;
    const int gid = lane >> 2, tig = lane & 3;
    const int warpM = (wid >> 2) * 64, warpN = (wid & 3) * 64;
    const int bz = blockIdx.z, by = blockIdx.y, t0 = blockIdx.x * 256;

    const uint32_t* Ah = g_ah32 + ((size_t)bz * Cn + by * 128) * 128;
    const uint32_t* Al = g_al32 + ((size_t)bz * Cn + by * 128) * 128;
    const uint32_t* Bh = g_xth32 + ((size_t)bz * Tn + t0) * 128;

    float acc[32][4];
#pragma unroll
    for (int a = 0; a < 32; a++)
#pragma unroll
        for (int c = 0; c < 4; c++) acc[a][c] = 0.f;

    const int frow = tid >> 3, fg = tid & 7;
    auto issue = [&](int c, int s) {
        uint32_t st = sb + s * 16384 * 4;
#pragma unroll
        for (int it = 0; it < 4; it++) {
            int row = frow + it * 32;
            int w4 = 4 * woff(row, fg);
            const uint32_t* src = Ah + (size_t)row * 128 + c * 32 + fg * 4;
            cp16(st + w4, src);
            cp16(st + 4096 * 4 + w4, Al + (size_t)row * 128 + c * 32 + fg * 4);
        }
#pragma unroll
        for (int it = 0; it < 8; it++) {
            int row = frow + it * 32;
            cp16(st + 8192 * 4 + 4 * woff(row, fg),
                 Bh + (size_t)row * 128 + c * 32 + fg * 4);
        }
    };

    issue(0, 0); CP_COMMIT();
    issue(1, 1); CP_COMMIT();
    CP_WAIT(1);
    __syncthreads();

    const int NC = Cn / 64;   // 4
#pragma unroll 1
    for (int c = 0; c < NC; c++) {
        const int s = c & 1;
        g2_chunk(sb + s * 16384 * 4, acc, warpM, warpN, lane);
        if (c + 1 < NC) {
            __syncthreads();
            if (c + 2 < NC) {
                issue(c + 2, s); CP_COMMIT();
                CP_WAIT(1);
            } else {
                CP_WAIT(0);
            }
            __syncthreads();
        }
    }

    const float gm = __ldg(gamma);
    const float* Xb = x + (size_t)bz * Cn * Tn;
    float* Ob = out + (size_t)bz * Cn * Tn;
#pragma unroll
    for (int ma = 0; ma < 4; ma++)
#pragma unroll
        for (int na = 0; na < 8; na++) {
            const float* d = acc[ma * 8 + na];
            int r0 = by * 128 + warpM + ma * 16 + gid;
            int cc = t0 + warpN + na * 8 + 2 * tig;
            size_t o0 = (size_t)r0 * Tn + cc;
            size_t o1 = (size_t)(r0 + 8) * Tn + cc;
            float2 x0 = *(const float2*)(Xb + o0);
            float2 x1 = *(const float2*)(Xb + o1);
            *(float2*)(Ob + o0) = make_float2(gm * d[0] + x0.x, gm * d[1] + x0.y);
            *(float2*)(Ob + o1) = make_float2(gm * d[2] + x1.x, gm * d[3] + x1.y);
        }
}

// ---------------------------------------------------------------------------
extern "C" void kernel_launch(void* const* d_in, const int* in_sizes, int n_in,
                              void* d_out, int out_size) {
    (void)in_sizes; (void)n_in; (void)out_size;
    const float* x = (const float*)d_in[0];
    const float* gamma = (const float*)d_in[1];
    float* out = (float*)d_out;

    const int smem = 32768 * 4;   // 128 KB for both GEMMs
    cudaFuncSetAttribute(gemm1_h, cudaFuncAttributeMaxDynamicSharedMemorySize, smem);
    cudaFuncSetAttribute(gemm2_h, cudaFuncAttributeMaxDynamicSharedMemorySize, smem);

    transpose_h<<<dim3(Tn / 32, Cn / 32, Bn), dim3(32, 8)>>>(x);
    gemm1_h<<<dim3(Cn / 128, Cn / 128, Bn), 256, smem>>>(x);
    softmax_kernel<<<Bn * Cn, 256>>>();
    gemm2_h<<<dim3(Tn / 256, Cn / 128, Bn), 256, smem>>>(x, gamma, out);
}

// round 11
// speedup vs baseline: 1.5303x; 1.5303x over previous
#include <cuda_runtime.h>
#include <cuda_fp16.h>
#include <cstdint>

#define Bn 32
#define Cn 256
#define Tn 4096

// Static device scratch (allocation-guard legal).
__device__ float4   g_e4[(size_t)Bn * Cn * Cn / 4];      //  8 MB energy (fp32)
__device__ uint32_t g_ah32[(size_t)Bn * Cn * Cn / 2];    //  4 MB attn hi (f16)
__device__ uint32_t g_al32[(size_t)Bn * Cn * Cn / 2];    //  4 MB attn lo (f16)
__device__ uint32_t g_xth32[(size_t)Bn * Tn * Cn / 2];   // 67 MB X^T hi (f16)

// ---------------------------------------------------------------------------
// Tile layout (R10-proven): row = 64 k f16 = 128 B = 32 words; 16B group g at
// word offset row*32 + (g^(row&7))*4. STS.128 / cp.async / LDSM conflict-free.
// ---------------------------------------------------------------------------
__device__ __forceinline__ int woff(int row, int g) {
    return row * 32 + ((g ^ (row & 7)) << 2);
}
__device__ __forceinline__ uint32_t smem_u32(const void* p) {
    uint32_t a;
    asm("{ .reg .u64 t; cvta.to.shared.u64 t, %1; cvt.u32.u64 %0, t; }"
        : "=r"(a) : "l"(p));
    return a;
}
__device__ __forceinline__ uint32_t packh2(__half a, __half b) {
    return (uint32_t)__half_as_ushort(a) | ((uint32_t)__half_as_ushort(b) << 16);
}
__device__ __forceinline__ void mma_f16(float* d, const uint32_t* a, const uint32_t* b) {
    asm volatile(
        "mma.sync.aligned.m16n8k16.row.col.f32.f16.f16.f32 "
        "{%0,%1,%2,%3}, {%4,%5,%6,%7}, {%8,%9}, {%0,%1,%2,%3};"
        : "+f"(d[0]), "+f"(d[1]), "+f"(d[2]), "+f"(d[3])
        : "r"(a[0]), "r"(a[1]), "r"(a[2]), "r"(a[3]), "r"(b[0]), "r"(b[1]));
}
__device__ __forceinline__ void ldsm4(uint32_t& r0, uint32_t& r1, uint32_t& r2,
                                      uint32_t& r3, uint32_t addr) {
    asm volatile("ldmatrix.sync.aligned.m8n8.x4.shared.b16 {%0,%1,%2,%3}, [%4];"
                 : "=r"(r0), "=r"(r1), "=r"(r2), "=r"(r3) : "r"(addr));
}
// A fragment (m16 x k16) at (mrow, ks).
__device__ __forceinline__ void lda_frag(uint32_t* a, uint32_t tb, int mrow,
                                         int ks, int lane) {
    int oct = lane >> 3, l7 = lane & 7;
    int row = mrow + ((oct & 1) << 3) + l7;
    int g = 2 * ks + (oct >> 1);
    ldsm4(a[0], a[1], a[2], a[3], tb + 4 * woff(row, g));
}
// B fragments for TWO n8-atoms (n16 x k16).
__device__ __forceinline__ void ldb_frag(uint32_t* b, uint32_t tb, int nrow,
                                         int ks, int lane) {
    int oct = lane >> 3, l7 = lane & 7;
    int row = nrow + ((oct >> 1) << 3) + l7;
    int g = 2 * ks + (oct & 1);
    ldsm4(b[0], b[1], b[2], b[3], tb + 4 * woff(row, g));
}
__device__ __forceinline__ void cp16(uint32_t saddr, const void* g) {
    asm volatile("cp.async.cg.shared.global [%0], [%1], 16;" :: "r"(saddr), "l"(g));
}
#define CP_COMMIT() asm volatile("cp.async.commit_group;" ::: "memory")
#define CP_WAIT(N)  asm volatile("cp.async.wait_group %0;" :: "n"(N) : "memory")

__device__ __forceinline__ void splitpack(float4 u, float4 v, uint4& H, uint4& L) {
    __half h0 = __float2half_rn(u.x), h1 = __float2half_rn(u.y);
    __half h2 = __float2half_rn(u.z), h3 = __float2half_rn(u.w);
    __half h4 = __float2half_rn(v.x), h5 = __float2half_rn(v.y);
    __half h6 = __float2half_rn(v.z), h7 = __float2half_rn(v.w);
    H = make_uint4(packh2(h0, h1), packh2(h2, h3), packh2(h4, h5), packh2(h6, h7));
    L = make_uint4(
        packh2(__float2half_rn(u.x - __half2float(h0)), __float2half_rn(u.y - __half2float(h1))),
        packh2(__float2half_rn(u.z - __half2float(h2)), __float2half_rn(u.w - __half2float(h3))),
        packh2(__float2half_rn(v.x - __half2float(h4)), __float2half_rn(v.y - __half2float(h5))),
        packh2(__float2half_rn(v.z - __half2float(h6)), __float2half_rn(v.w - __half2float(h7))));
}

// ---------------------------------------------------------------------------
// Transpose + f16-round: xt_h[b][t][c] = f16(x[b][c][t])
// ---------------------------------------------------------------------------
__global__ __launch_bounds__(256) void transpose_h(const float* __restrict__ x) {
    __shared__ float tile[32][33];
    const int b = blockIdx.z, c0 = blockIdx.y * 32, t0 = blockIdx.x * 32;
    const int tx = threadIdx.x, ty = threadIdx.y;
    const float* Xb = x + ((size_t)b * Cn + c0) * Tn + t0;
    __half* Xt = (__half*)g_xth32 + ((size_t)b * Tn + t0) * Cn + c0;
#pragma unroll
    for (int r = 0; r < 32; r += 8) tile[ty + r][tx] = Xb[(size_t)(ty + r) * Tn + tx];
    __syncthreads();
#pragma unroll
    for (int r = 0; r < 32; r += 8)
        Xt[(size_t)(ty + r) * Cn + tx] = __float2half_rn(tile[tx][ty + r]);
}

// ---------------------------------------------------------------------------
// GEMM1: E[b] = X[b]*X[b]^T, 3xFP16. CTA 128x128, 16 warps (32x32 tiles), BK=64.
// Stage words: AH 0, AL 4096, BH 8192, BL 12288; stage stride 16384 (128 KB).
// ---------------------------------------------------------------------------
__device__ __forceinline__ void g1_chunk(uint32_t sbase, float acc[8][4],
                                         int warpM, int warpN, int lane) {
    const uint32_t AH = sbase, AL = sbase + 4096 * 4;
    const uint32_t BH = sbase + 8192 * 4, BL = sbase + 12288 * 4;
#pragma unroll
    for (int ks = 0; ks < 4; ks++) {
        uint32_t ah[2][4], al[2][4], bh[4][2], bl[4][2];
#pragma unroll
        for (int ma = 0; ma < 2; ma++) lda_frag(ah[ma], AH, warpM + ma * 16, ks, lane);
#pragma unroll
        for (int ma = 0; ma < 2; ma++) lda_frag(al[ma], AL, warpM + ma * 16, ks, lane);
        ldb_frag(&bh[0][0], BH, warpN, ks, lane);
        ldb_frag(&bh[2][0], BH, warpN + 16, ks, lane);
        ldb_frag(&bl[0][0], BL, warpN, ks, lane);
        ldb_frag(&bl[2][0], BL, warpN + 16, ks, lane);
#pragma unroll
        for (int ma = 0; ma < 2; ma++)
#pragma unroll
            for (int na = 0; na < 4; na++) {
                float* d = acc[ma * 4 + na];
                mma_f16(d, ah[ma], bh[na]);
                mma_f16(d, al[ma], bh[na]);
                mma_f16(d, ah[ma], bl[na]);
            }
    }
}

__global__ __launch_bounds__(512, 1) void gemm1_h(const float* __restrict__ x) {
    extern __shared__ uint32_t sm[];
    const uint32_t sb = smem_u32(sm);
    const int tid = threadIdx.x, lane = tid & 31, wid = tid >> 5;
    const int gid = lane >> 2, tig = lane & 3;
    const int warpM = (wid >> 2) * 32, warpN = (wid & 3) * 32;
    const float* Xb = x + (size_t)blockIdx.z * Cn * Tn;
    const float* Ag = Xb + (size_t)blockIdx.y * 128 * Tn;
    const float* Bg = Xb + (size_t)blockIdx.x * 128 * Tn;

    float acc[8][4];
#pragma unroll
    for (int a = 0; a < 8; a++)
#pragma unroll
        for (int c = 0; c < 4; c++) acc[a][c] = 0.f;

    // Fetch map: cell idx = it*512+tid -> (row = idx>>3, g = idx&7); 2 cells.
    float4 va[4], vb[4];
    auto fetch = [&](int c) {
#pragma unroll
        for (int it = 0; it < 2; it++) {
            int idx = it * 512 + tid, row = idx >> 3, g = idx & 7;
            const float* pa = Ag + (size_t)row * Tn + c * 64 + g * 8;
            const float* pb = Bg + (size_t)row * Tn + c * 64 + g * 8;
            va[2 * it] = *(const float4*)pa;  va[2 * it + 1] = *(const float4*)(pa + 4);
            vb[2 * it] = *(const float4*)pb;  vb[2 * it + 1] = *(const float4*)(pb + 4);
        }
    };
    auto stage = [&](int s) {
        uint32_t* st = sm + s * 16384;
#pragma unroll
        for (int it = 0; it < 2; it++) {
            int idx = it * 512 + tid, row = idx >> 3, g = idx & 7;
            int w = woff(row, g);
            uint4 H, L;
            splitpack(va[2 * it], va[2 * it + 1], H, L);
            *(uint4*)(st + w) = H;
            *(uint4*)(st + 4096 + w) = L;
            splitpack(vb[2 * it], vb[2 * it + 1], H, L);
            *(uint4*)(st + 8192 + w) = H;
            *(uint4*)(st + 12288 + w) = L;
        }
    };

    fetch(0);
    stage(0);
    __syncthreads();

    const int NC = Tn / 64;
#pragma unroll 1
    for (int c = 0; c < NC; c++) {
        const int s = c & 1;
        if (c + 1 < NC) fetch(c + 1);
        g1_chunk(sb + s * 16384 * 4, acc, warpM, warpN, lane);
        if (c + 1 < NC) {
            stage(s ^ 1);
            __syncthreads();
        }
    }

    float* E = (float*)g_e4 + (size_t)blockIdx.z * Cn * Cn;
#pragma unroll
    for (int ma = 0; ma < 2; ma++)
#pragma unroll
        for (int na = 0; na < 4; na++) {
            const float* d = acc[ma * 4 + na];
            int r0 = blockIdx.y * 128 + warpM + ma * 16 + gid;
            int cc = blockIdx.x * 128 + warpN + na * 8 + 2 * tig;
            *(float2*)(E + (size_t)r0 * Cn + cc) = make_float2(d[0], d[1]);
            *(float2*)(E + (size_t)(r0 + 8) * Cn + cc) = make_float2(d[2], d[3]);
        }
}

// ---------------------------------------------------------------------------
// Softmax: w = exp(min_e - e)/sum (== softmax(rowmax - e)); writes f16 h+l.
// ---------------------------------------------------------------------------
__global__ __launch_bounds__(256) void softmax_kernel() {
    const int row = blockIdx.x;
    const float* E = (float*)g_e4 + (size_t)row * Cn;
    const int tid = threadIdx.x;

    float e = E[tid];
    float v = e;
#pragma unroll
    for (int o = 16; o; o >>= 1) v = fminf(v, __shfl_xor_sync(0xffffffffu, v, o));
    __shared__ float red[8];
    __shared__ float bc[2];
    if ((tid & 31) == 0) red[tid >> 5] = v;
    __syncthreads();
    if (tid == 0) {
        float m = red[0];
#pragma unroll
        for (int i = 1; i < 8; i++) m = fminf(m, red[i]);
        bc[0] = m;
    }
    __syncthreads();
    float p = expf(bc[0] - e);
    v = p;
#pragma unroll
    for (int o = 16; o; o >>= 1) v += __shfl_xor_sync(0xffffffffu, v, o);
    if ((tid & 31) == 0) red[tid >> 5] = v;
    __syncthreads();
    if (tid == 0) {
        float s = 0.f;
#pragma unroll
        for (int i = 0; i < 8; i++) s += red[i];
        bc[1] = 1.0f / s;
    }
    __syncthreads();
    float w = p * bc[1];
    __half h = __float2half_rn(w);
    ((__half*)g_ah32)[(size_t)row * Cn + tid] = h;
    ((__half*)g_al32)[(size_t)row * Cn + tid] =
        __float2half_rn(w - __half2float(h));
}

// ---------------------------------------------------------------------------
// GEMM2: out = gamma*(Attn*X) + X. CTA 128x256, 16 warps (32x64 tiles), BK=64.
// All operands pre-split f16 -> cp.async 2-stage pipeline.
// Stage words: AH 0, AL 4096, BH 8192..16383; stride 16384 (128 KB total).
// ---------------------------------------------------------------------------
__device__ __forceinline__ void g2_chunk(uint32_t sbase, float acc[16][4],
                                         int warpM, int warpN, int lane) {
    const uint32_t AH = sbase, AL = sbase + 4096 * 4, BH = sbase + 8192 * 4;
#pragma unroll
    for (int ks = 0; ks < 4; ks++) {
        uint32_t ah[2][4], al[2][4], bh[8][2];
#pragma unroll
        for (int ma = 0; ma < 2; ma++) lda_frag(ah[ma], AH, warpM + ma * 16, ks, lane);
#pragma unroll
        for (int ma = 0; ma < 2; ma++) lda_frag(al[ma], AL, warpM + ma * 16, ks, lane);
#pragma unroll
        for (int p = 0; p < 4; p++) ldb_frag(&bh[2 * p][0], BH, warpN + p * 16, ks, lane);
#pragma unroll
        for (int ma = 0; ma < 2; ma++)
#pragma unroll
            for (int na = 0; na < 8; na++) {
                float* d = acc[ma * 8 + na];
                mma_f16(d, ah[ma], bh[na]);
                mma_f16(d, al[ma], bh[na]);
            }
    }
}

__global__ __launch_bounds__(512, 1) void gemm2_h(const float* __restrict__ x,
                                                  const float* __restrict__ gamma,
                                                  float* __restrict__ out) {
    extern __shared__ uint32_t sm[];
    const uint32_t sb = smem_u32(sm);
    const int tid = threadIdx.x, lane = tid & 31, wid = tid >> 5;
    const int gid = lane >> 2, tig = lane & 3;
    const int warpM = (wid >> 2) * 32, warpN = (wid & 3) * 64;
    const int bz = blockIdx.z, by = blockIdx.y, t0 = blockIdx.x * 256;

    const uint32_t* Ah = g_ah32 + ((size_t)bz * Cn + by * 128) * 128;
    const uint32_t* Al = g_al32 + ((size_t)bz * Cn + by * 128) * 128;
    const uint32_t* Bh = g_xth32 + ((size_t)bz * Tn + t0) * 128;

    float acc[16][4];
#pragma unroll
    for (int a = 0; a < 16; a++)
#pragma unroll
        for (int c = 0; c < 4; c++) acc[a][c] = 0.f;

    auto issue = [&](int c, int s) {
        uint32_t st = sb + s * 16384 * 4;
        // A tiles: 1024 cells each -> 2 per thread.
#pragma unroll
        for (int it = 0; it < 2; it++) {
            int idx = it * 512 + tid, row = idx >> 3, g = idx & 7;
            int w4 = 4 * woff(row, g);
            cp16(st + w4, Ah + (size_t)row * 128 + c * 32 + g * 4);
            cp16(st + 4096 * 4 + w4, Al + (size_t)row * 128 + c * 32 + g * 4);
        }
        // B tile: 256 rows x 8 g = 2048 cells -> 4 per thread.
#pragma unroll
        for (int it = 0; it < 4; it++) {
            int idx = it * 512 + tid, row = idx >> 3, g = idx & 7;
            cp16(st + 8192 * 4 + 4 * woff(row, g),
                 Bh + (size_t)row * 128 + c * 32 + g * 4);
        }
    };

    issue(0, 0); CP_COMMIT();
    issue(1, 1); CP_COMMIT();
    CP_WAIT(1);
    __syncthreads();

    const int NC = Cn / 64;   // 4
#pragma unroll 1
    for (int c = 0; c < NC; c++) {
        const int s = c & 1;
        g2_chunk(sb + s * 16384 * 4, acc, warpM, warpN, lane);
        if (c + 1 < NC) {
            __syncthreads();
            if (c + 2 < NC) {
                issue(c + 2, s); CP_COMMIT();
                CP_WAIT(1);
            } else {
                CP_WAIT(0);
            }
            __syncthreads();
        }
    }

    const float gm = __ldg(gamma);
    const float* Xb = x + (size_t)bz * Cn * Tn;
    float* Ob = out + (size_t)bz * Cn * Tn;
#pragma unroll
    for (int ma = 0; ma < 2; ma++)
#pragma unroll
        for (int na = 0; na < 8; na++) {
            const float* d = acc[ma * 8 + na];
            int r0 = by * 128 + warpM + ma * 16 + gid;
            int cc = t0 + warpN + na * 8 + 2 * tig;
            size_t o0 = (size_t)r0 * Tn + cc;
            size_t o1 = (size_t)(r0 + 8) * Tn + cc;
            float2 x0 = *(const float2*)(Xb + o0);
            float2 x1 = *(const float2*)(Xb + o1);
            *(float2*)(Ob + o0) = make_float2(gm * d[0] + x0.x, gm * d[1] + x0.y);
            *(float2*)(Ob + o1) = make_float2(gm * d[2] + x1.x, gm * d[3] + x1.y);
        }
}

// ---------------------------------------------------------------------------
extern "C" void kernel_launch(void* const* d_in, const int* in_sizes, int n_in,
                              void* d_out, int out_size) {
    (void)in_sizes; (void)n_in; (void)out_size;
    const float* x = (const float*)d_in[0];
    const float* gamma = (const float*)d_in[1];
    float* out = (float*)d_out;

    const int smem = 32768 * 4;   // 128 KB for both GEMMs
    cudaFuncSetAttribute(gemm1_h, cudaFuncAttributeMaxDynamicSharedMemorySize, smem);
    cudaFuncSetAttribute(gemm2_h, cudaFuncAttributeMaxDynamicSharedMemorySize, smem);

    transpose_h<<<dim3(Tn / 32, Cn / 32, Bn), dim3(32, 8)>>>(x);
    gemm1_h<<<dim3(Cn / 128, Cn / 128, Bn), 512, smem>>>(x);
    softmax_kernel<<<Bn * Cn, 256>>>();
    gemm2_h<<<dim3(Tn / 256, Cn / 128, Bn), 512, smem>>>(x, gamma, out);
}

// round 12
// speedup vs baseline: 1.7439x; 1.1396x over previous
#include <cuda_runtime.h>
#include <cuda_fp16.h>
#include <cstdint>

#define Bn 32
#define Cn 256
#define Tn 4096

// Static device scratch (allocation-guard legal).
__device__ float4   g_e4[(size_t)Bn * Cn * Cn / 4];      //  8 MB energy (fp32)
__device__ uint32_t g_ah32[(size_t)Bn * Cn * Cn / 2];    //  4 MB attn hi (f16)
__device__ uint32_t g_al32[(size_t)Bn * Cn * Cn / 2];    //  4 MB attn lo (f16)
__device__ uint32_t g_xh32[(size_t)Bn * Cn * Tn / 2];    // 67 MB X hi  row-major
__device__ uint32_t g_xl32[(size_t)Bn * Cn * Tn / 2];    // 67 MB X lo  row-major
__device__ uint32_t g_xth32[(size_t)Bn * Tn * Cn / 2];   // 67 MB X^T hi

// ---------------------------------------------------------------------------
// Tile layout (proven): row = 64 k f16 = 128 B = 32 words; 16B group g at
// word offset row*32 + (g^(row&7))*4. cp.async / LDSM conflict-free.
// ---------------------------------------------------------------------------
__device__ __forceinline__ int woff(int row, int g) {
    return row * 32 + ((g ^ (row & 7)) << 2);
}
__device__ __forceinline__ uint32_t smem_u32(const void* p) {
    uint32_t a;
    asm("{ .reg .u64 t; cvta.to.shared.u64 t, %1; cvt.u32.u64 %0, t; }"
        : "=r"(a) : "l"(p));
    return a;
}
__device__ __forceinline__ uint32_t packh2(__half a, __half b) {
    return (uint32_t)__half_as_ushort(a) | ((uint32_t)__half_as_ushort(b) << 16);
}
__device__ __forceinline__ void mma_f16(float* d, const uint32_t* a, const uint32_t* b) {
    asm volatile(
        "mma.sync.aligned.m16n8k16.row.col.f32.f16.f16.f32 "
        "{%0,%1,%2,%3}, {%4,%5,%6,%7}, {%8,%9}, {%0,%1,%2,%3};"
        : "+f"(d[0]), "+f"(d[1]), "+f"(d[2]), "+f"(d[3])
        : "r"(a[0]), "r"(a[1]), "r"(a[2]), "r"(a[3]), "r"(b[0]), "r"(b[1]));
}
__device__ __forceinline__ void ldsm4(uint32_t& r0, uint32_t& r1, uint32_t& r2,
                                      uint32_t& r3, uint32_t addr) {
    asm volatile("ldmatrix.sync.aligned.m8n8.x4.shared.b16 {%0,%1,%2,%3}, [%4];"
                 : "=r"(r0), "=r"(r1), "=r"(r2), "=r"(r3) : "r"(addr));
}
__device__ __forceinline__ void lda_frag(uint32_t* a, uint32_t tb, int mrow,
                                         int ks, int lane) {
    int oct = lane >> 3, l7 = lane & 7;
    int row = mrow + ((oct & 1) << 3) + l7;
    int g = 2 * ks + (oct >> 1);
    ldsm4(a[0], a[1], a[2], a[3], tb + 4 * woff(row, g));
}
__device__ __forceinline__ void ldb_frag(uint32_t* b, uint32_t tb, int nrow,
                                         int ks, int lane) {
    int oct = lane >> 3, l7 = lane & 7;
    int row = nrow + ((oct >> 1) << 3) + l7;
    int g = 2 * ks + (oct & 1);
    ldsm4(b[0], b[1], b[2], b[3], tb + 4 * woff(row, g));
}
__device__ __forceinline__ void cp16(uint32_t saddr, const void* g) {
    asm volatile("cp.async.cg.shared.global [%0], [%1], 16;" :: "r"(saddr), "l"(g));
}
#define CP_COMMIT() asm volatile("cp.async.commit_group;" ::: "memory")
#define CP_WAIT(N)  asm volatile("cp.async.wait_group %0;" :: "n"(N) : "memory")

// ---------------------------------------------------------------------------
// Prepass: one read of X -> Xh (rm), Xl (rm), Xth (transposed hi), all f16.
// Tile 32c x 64t, 256 threads, grid (64, 8, 32).
// ---------------------------------------------------------------------------
__global__ __launch_bounds__(256) void split_pre(const float* __restrict__ x) {
    __shared__ __half tile[64][34];
    const int b = blockIdx.z, c0 = blockIdx.y * 32, t0 = blockIdx.x * 64;
    const int tid = threadIdx.x, cl = tid >> 5, t2 = tid & 31;
    const float* Xb = x + ((size_t)b * Cn + c0) * Tn + t0;
    uint32_t* Xh = g_xh32 + ((size_t)b * Cn + c0) * (Tn / 2) + t0 / 2;
    uint32_t* Xl = g_xl32 + ((size_t)b * Cn + c0) * (Tn / 2) + t0 / 2;
#pragma unroll
    for (int i = 0; i < 4; i++) {
        int c = cl + 8 * i;
        float2 v = *(const float2*)(Xb + (size_t)c * Tn + 2 * t2);
        __half h0 = __float2half_rn(v.x), h1 = __float2half_rn(v.y);
        Xh[(size_t)c * (Tn / 2) + t2] = packh2(h0, h1);
        Xl[(size_t)c * (Tn / 2) + t2] =
            packh2(__float2half_rn(v.x - __half2float(h0)),
                   __float2half_rn(v.y - __half2float(h1)));
        tile[2 * t2][c] = h0;
        tile[2 * t2 + 1][c] = h1;
    }
    __syncthreads();
    uint32_t* Xt = g_xth32 + ((size_t)b * Tn + t0) * (Cn / 2) + c0 / 2;
    const int tl = tid >> 4, c2 = tid & 15;
#pragma unroll
    for (int i = 0; i < 4; i++) {
        int t = tl + 16 * i;
        Xt[(size_t)t * (Cn / 2) + c2] = packh2(tile[t][2 * c2], tile[t][2 * c2 + 1]);
    }
}

// ---------------------------------------------------------------------------
// GEMM1: E[b] = X[b]*X[b]^T, 3xFP16, all-cp.async. CTA 128x128, 16 warps
// (32x32 tiles), BK=64, 3-stage. Stage words: AH 0, AL 4096, BH 8192, BL 12288.
// ---------------------------------------------------------------------------
__device__ __forceinline__ void g1_chunk(uint32_t sbase, float acc[8][4],
                                         int warpM, int warpN, int lane) {
    const uint32_t AH = sbase, AL = sbase + 4096 * 4;
    const uint32_t BH = sbase + 8192 * 4, BL = sbase + 12288 * 4;
#pragma unroll
    for (int ks = 0; ks < 4; ks++) {
        uint32_t ah[2][4], al[2][4], bh[4][2], bl[4][2];
#pragma unroll
        for (int ma = 0; ma < 2; ma++) lda_frag(ah[ma], AH, warpM + ma * 16, ks, lane);
#pragma unroll
        for (int ma = 0; ma < 2; ma++) lda_frag(al[ma], AL, warpM + ma * 16, ks, lane);
        ldb_frag(&bh[0][0], BH, warpN, ks, lane);
        ldb_frag(&bh[2][0], BH, warpN + 16, ks, lane);
        ldb_frag(&bl[0][0], BL, warpN, ks, lane);
        ldb_frag(&bl[2][0], BL, warpN + 16, ks, lane);
#pragma unroll
        for (int ma = 0; ma < 2; ma++)
#pragma unroll
            for (int na = 0; na < 4; na++) {
                float* d = acc[ma * 4 + na];
                mma_f16(d, ah[ma], bh[na]);
                mma_f16(d, al[ma], bh[na]);
                mma_f16(d, ah[ma], bl[na]);
            }
    }
}

__global__ __launch_bounds__(512, 1) void gemm1_h() {
    extern __shared__ uint32_t sm[];
    const uint32_t sb = smem_u32(sm);
    const int tid = threadIdx.x, lane = tid & 31, wid = tid >> 5;
    const int gid = lane >> 2, tig = lane & 3;
    const int warpM = (wid >> 2) * 32, warpN = (wid & 3) * 32;
    const size_t pa = ((size_t)blockIdx.z * Cn + blockIdx.y * 128) * (Tn / 2);
    const size_t pb = ((size_t)blockIdx.z * Cn + blockIdx.x * 128) * (Tn / 2);
    const uint32_t* Ahp = g_xh32 + pa;
    const uint32_t* Alp = g_xl32 + pa;
    const uint32_t* Bhp = g_xh32 + pb;
    const uint32_t* Blp = g_xl32 + pb;

    float acc[8][4];
#pragma unroll
    for (int a = 0; a < 8; a++)
#pragma unroll
        for (int c = 0; c < 4; c++) acc[a][c] = 0.f;

    auto issue = [&](int c, int s) {
        uint32_t st = sb + s * 16384 * 4;
#pragma unroll
        for (int it = 0; it < 2; it++) {
            int idx = it * 512 + tid, row = idx >> 3, g = idx & 7;
            int w4 = 4 * woff(row, g);
            size_t go = (size_t)row * (Tn / 2) + c * 32 + g * 4;
            cp16(st + w4, Ahp + go);
            cp16(st + 4096 * 4 + w4, Alp + go);
            cp16(st + 8192 * 4 + w4, Bhp + go);
            cp16(st + 12288 * 4 + w4, Blp + go);
        }
    };

    issue(0, 0); CP_COMMIT();
    issue(1, 1); CP_COMMIT();
    issue(2, 2); CP_COMMIT();
    CP_WAIT(2);
    __syncthreads();

    const int NC = Tn / 64;   // 64
#pragma unroll 1
    for (int c = 0; c < NC; c++) {
        g1_chunk(sb + (c % 3) * 16384 * 4, acc, warpM, warpN, lane);
        if (c + 1 < NC) {
            __syncthreads();
            if (c + 3 < NC) issue(c + 3, c % 3);
            CP_COMMIT();           // always commit (possibly empty) - keeps FIFO depth
            CP_WAIT(2);            // ensures chunk c+1's group is complete
            __syncthreads();
        }
    }

    float* E = (float*)g_e4 + (size_t)blockIdx.z * Cn * Cn;
#pragma unroll
    for (int ma = 0; ma < 2; ma++)
#pragma unroll
        for (int na = 0; na < 4; na++) {
            const float* d = acc[ma * 4 + na];
            int r0 = blockIdx.y * 128 + warpM + ma * 16 + gid;
            int cc = blockIdx.x * 128 + warpN + na * 8 + 2 * tig;
            *(float2*)(E + (size_t)r0 * Cn + cc) = make_float2(d[0], d[1]);
            *(float2*)(E + (size_t)(r0 + 8) * Cn + cc) = make_float2(d[2], d[3]);
        }
}

// ---------------------------------------------------------------------------
// Softmax: w = exp(min_e - e)/sum (== softmax(rowmax - e)); writes f16 h+l.
// ---------------------------------------------------------------------------
__global__ __launch_bounds__(256) void softmax_kernel() {
    const int row = blockIdx.x;
    const float* E = (float*)g_e4 + (size_t)row * Cn;
    const int tid = threadIdx.x;

    float e = E[tid];
    float v = e;
#pragma unroll
    for (int o = 16; o; o >>= 1) v = fminf(v, __shfl_xor_sync(0xffffffffu, v, o));
    __shared__ float red[8];
    __shared__ float bc[2];
    if ((tid & 31) == 0) red[tid >> 5] = v;
    __syncthreads();
    if (tid == 0) {
        float m = red[0];
#pragma unroll
        for (int i = 1; i < 8; i++) m = fminf(m, red[i]);
        bc[0] = m;
    }
    __syncthreads();
    float p = expf(bc[0] - e);
    v = p;
#pragma unroll
    for (int o = 16; o; o >>= 1) v += __shfl_xor_sync(0xffffffffu, v, o);
    if ((tid & 31) == 0) red[tid >> 5] = v;
    __syncthreads();
    if (tid == 0) {
        float s = 0.f;
#pragma unroll
        for (int i = 0; i < 8; i++) s += red[i];
        bc[1] = 1.0f / s;
    }
    __syncthreads();
    float w = p * bc[1];
    __half h = __float2half_rn(w);
    ((__half*)g_ah32)[(size_t)row * Cn + tid] = h;
    ((__half*)g_al32)[(size_t)row * Cn + tid] =
        __float2half_rn(w - __half2float(h));
}

// ---------------------------------------------------------------------------
// GEMM2: out = gamma*(Attn*X) + X. CTA 128x256, 16 warps (32x64 tiles), BK=64,
// 3-stage cp.async. Stage words: AH 0, AL 4096, BH 8192..16383.
// ---------------------------------------------------------------------------
__device__ __forceinline__ void g2_chunk(uint32_t sbase, float acc[16][4],
                                         int warpM, int warpN, int lane) {
    const uint32_t AH = sbase, AL = sbase + 4096 * 4, BH = sbase + 8192 * 4;
#pragma unroll
    for (int ks = 0; ks < 4; ks++) {
        uint32_t ah[2][4], al[2][4], bh[8][2];
#pragma unroll
        for (int ma = 0; ma < 2; ma++) lda_frag(ah[ma], AH, warpM + ma * 16, ks, lane);
#pragma unroll
        for (int ma = 0; ma < 2; ma++) lda_frag(al[ma], AL, warpM + ma * 16, ks, lane);
#pragma unroll
        for (int p = 0; p < 4; p++) ldb_frag(&bh[2 * p][0], BH, warpN + p * 16, ks, lane);
#pragma unroll
        for (int ma = 0; ma < 2; ma++)
#pragma unroll
            for (int na = 0; na < 8; na++) {
                float* d = acc[ma * 8 + na];
                mma_f16(d, ah[ma], bh[na]);
                mma_f16(d, al[ma], bh[na]);
            }
    }
}

__global__ __launch_bounds__(512, 1) void gemm2_h(const float* __restrict__ x,
                                                  const float* __restrict__ gamma,
                                                  float* __restrict__ out) {
    extern __shared__ uint32_t sm[];
    const uint32_t sb = smem_u32(sm);
    const int tid = threadIdx.x, lane = tid & 31, wid = tid >> 5;
    const int gid = lane >> 2, tig = lane & 3;
    const int warpM = (wid >> 2) * 32, warpN = (wid & 3) * 64;
    const int bz = blockIdx.z, by = blockIdx.y, t0 = blockIdx.x * 256;

    const uint32_t* Ah = g_ah32 + ((size_t)bz * Cn + by * 128) * 128;
    const uint32_t* Al = g_al32 + ((size_t)bz * Cn + by * 128) * 128;
    const uint32_t* Bh = g_xth32 + ((size_t)bz * Tn + t0) * 128;

    float acc[16][4];
#pragma unroll
    for (int a = 0; a < 16; a++)
#pragma unroll
        for (int c = 0; c < 4; c++) acc[a][c] = 0.f;

    auto issue = [&](int c, int s) {
        uint32_t st = sb + s * 16384 * 4;
#pragma unroll
        for (int it = 0; it < 2; it++) {
            int idx = it * 512 + tid, row = idx >> 3, g = idx & 7;
            int w4 = 4 * woff(row, g);
            cp16(st + w4, Ah + (size_t)row * 128 + c * 32 + g * 4);
            cp16(st + 4096 * 4 + w4, Al + (size_t)row * 128 + c * 32 + g * 4);
        }
#pragma unroll
        for (int it = 0; it < 4; it++) {
            int idx = it * 512 + tid, row = idx >> 3, g = idx & 7;
            cp16(st + 8192 * 4 + 4 * woff(row, g),
                 Bh + (size_t)row * 128 + c * 32 + g * 4);
        }
    };

    issue(0, 0); CP_COMMIT();
    issue(1, 1); CP_COMMIT();
    issue(2, 2); CP_COMMIT();
    CP_WAIT(2);
    __syncthreads();

    const int NC = Cn / 64;   // 4
#pragma unroll 1
    for (int c = 0; c < NC; c++) {
        g2_chunk(sb + (c % 3) * 16384 * 4, acc, warpM, warpN, lane);
        if (c + 1 < NC) {
            __syncthreads();
            if (c + 3 < NC) issue(c + 3, c % 3);
            CP_COMMIT();
            CP_WAIT(2);
            __syncthreads();
        }
    }

    const float gm = __ldg(gamma);
    const float* Xb = x + (size_t)bz * Cn * Tn;
    float* Ob = out + (size_t)bz * Cn * Tn;
#pragma unroll
    for (int ma = 0; ma < 2; ma++)
#pragma unroll
        for (int na = 0; na < 8; na++) {
            const float* d = acc[ma * 8 + na];
            int r0 = by * 128 + warpM + ma * 16 + gid;
            int cc = t0 + warpN + na * 8 + 2 * tig;
            size_t o0 = (size_t)r0 * Tn + cc;
            size_t o1 = (size_t)(r0 + 8) * Tn + cc;
            float2 x0 = *(const float2*)(Xb + o0);
            float2 x1 = *(const float2*)(Xb + o1);
            *(float2*)(Ob + o0) = make_float2(gm * d[0] + x0.x, gm * d[1] + x0.y);
            *(float2*)(Ob + o1) = make_float2(gm * d[2] + x1.x, gm * d[3] + x1.y);
        }
}

// ---------------------------------------------------------------------------
extern "C" void kernel_launch(void* const* d_in, const int* in_sizes, int n_in,
                              void* d_out, int out_size) {
    (void)in_sizes; (void)n_in; (void)out_size;
    const float* x = (const float*)d_in[0];
    const float* gamma = (const float*)d_in[1];
    float* out = (float*)d_out;

    const int smem = 3 * 16384 * 4;   // 192 KB, 3 stages, both GEMMs
    cudaFuncSetAttribute(gemm1_h, cudaFuncAttributeMaxDynamicSharedMemorySize, smem);
    cudaFuncSetAttribute(gemm2_h, cudaFuncAttributeMaxDynamicSharedMemorySize, smem);

    split_pre<<<dim3(Tn / 64, Cn / 32, Bn), 256>>>(x);
    gemm1_h<<<dim3(Cn / 128, Cn / 128, Bn), 512, smem>>>();
    softmax_kernel<<<Bn * Cn, 256>>>();
    gemm2_h<<<dim3(Tn / 256, Cn / 128, Bn), 512, smem>>>(x, gamma, out);
}

// round 13
// speedup vs baseline: 2.1932x; 1.2577x over previous
#include <cuda_runtime.h>
#include <cuda_fp16.h>
#include <cstdint>

#define Bn 32
#define Cn 256
#define Tn 4096

// Static device scratch (allocation-guard legal).
__device__ float4   g_e4[(size_t)Bn * Cn * Cn / 4];      //  8 MB P = S + M (fp32)
__device__ float4   g_m4[(size_t)Bn * Cn * Cn / 4];      //  8 MB M = Xl*Xh^T (fp32)
__device__ uint32_t g_ah32[(size_t)Bn * Cn * Cn / 2];    //  4 MB attn hi (f16)
__device__ uint32_t g_al32[(size_t)Bn * Cn * Cn / 2];    //  4 MB attn lo (f16)
__device__ uint32_t g_xh32[(size_t)Bn * Cn * Tn / 2];    // 67 MB X hi  row-major
__device__ uint32_t g_xl32[(size_t)Bn * Cn * Tn / 2];    // 67 MB X lo  row-major
__device__ uint32_t g_xth32[(size_t)Bn * Tn * Cn / 2];   // 67 MB X^T hi

// ---------------------------------------------------------------------------
// Tile layout (proven): row = 64 k f16 = 128 B = 32 words; 16B group g at
// word offset row*32 + (g^(row&7))*4. cp.async / LDSM conflict-free.
// ---------------------------------------------------------------------------
__device__ __forceinline__ int woff(int row, int g) {
    return row * 32 + ((g ^ (row & 7)) << 2);
}
__device__ __forceinline__ uint32_t smem_u32(const void* p) {
    uint32_t a;
    asm("{ .reg .u64 t; cvta.to.shared.u64 t, %1; cvt.u32.u64 %0, t; }"
        : "=r"(a) : "l"(p));
    return a;
}
__device__ __forceinline__ uint32_t packh2(__half a, __half b) {
    return (uint32_t)__half_as_ushort(a) | ((uint32_t)__half_as_ushort(b) << 16);
}
__device__ __forceinline__ void mma_f16(float* d, const uint32_t* a, const uint32_t* b) {
    asm volatile(
        "mma.sync.aligned.m16n8k16.row.col.f32.f16.f16.f32 "
        "{%0,%1,%2,%3}, {%4,%5,%6,%7}, {%8,%9}, {%0,%1,%2,%3};"
        : "+f"(d[0]), "+f"(d[1]), "+f"(d[2]), "+f"(d[3])
        : "r"(a[0]), "r"(a[1]), "r"(a[2]), "r"(a[3]), "r"(b[0]), "r"(b[1]));
}
__device__ __forceinline__ void ldsm4(uint32_t& r0, uint32_t& r1, uint32_t& r2,
                                      uint32_t& r3, uint32_t addr) {
    asm volatile("ldmatrix.sync.aligned.m8n8.x4.shared.b16 {%0,%1,%2,%3}, [%4];"
                 : "=r"(r0), "=r"(r1), "=r"(r2), "=r"(r3) : "r"(addr));
}
__device__ __forceinline__ void lda_frag(uint32_t* a, uint32_t tb, int mrow,
                                         int ks, int lane) {
    int oct = lane >> 3, l7 = lane & 7;
    int row = mrow + ((oct & 1) << 3) + l7;
    int g = 2 * ks + (oct >> 1);
    ldsm4(a[0], a[1], a[2], a[3], tb + 4 * woff(row, g));
}
__device__ __forceinline__ void ldb_frag(uint32_t* b, uint32_t tb, int nrow,
                                         int ks, int lane) {
    int oct = lane >> 3, l7 = lane & 7;
    int row = nrow + ((oct >> 1) << 3) + l7;
    int g = 2 * ks + (oct & 1);
    ldsm4(b[0], b[1], b[2], b[3], tb + 4 * woff(row, g));
}
__device__ __forceinline__ void cp16(uint32_t saddr, const void* g) {
    asm volatile("cp.async.cg.shared.global [%0], [%1], 16;" :: "r"(saddr), "l"(g));
}
#define CP_COMMIT() asm volatile("cp.async.commit_group;" ::: "memory")
#define CP_WAIT(N)  asm volatile("cp.async.wait_group %0;" :: "n"(N) : "memory")

// ---------------------------------------------------------------------------
// Prepass: one read of X -> Xh (rm), Xl (rm), Xth (transposed hi), all f16.
// ---------------------------------------------------------------------------
__global__ __launch_bounds__(256) void split_pre(const float* __restrict__ x) {
    __shared__ __half tile[64][34];
    const int b = blockIdx.z, c0 = blockIdx.y * 32, t0 = blockIdx.x * 64;
    const int tid = threadIdx.x, cl = tid >> 5, t2 = tid & 31;
    const float* Xb = x + ((size_t)b * Cn + c0) * Tn + t0;
    uint32_t* Xh = g_xh32 + ((size_t)b * Cn + c0) * (Tn / 2) + t0 / 2;
    uint32_t* Xl = g_xl32 + ((size_t)b * Cn + c0) * (Tn / 2) + t0 / 2;
#pragma unroll
    for (int i = 0; i < 4; i++) {
        int c = cl + 8 * i;
        float2 v = *(const float2*)(Xb + (size_t)c * Tn + 2 * t2);
        __half h0 = __float2half_rn(v.x), h1 = __float2half_rn(v.y);
        Xh[(size_t)c * (Tn / 2) + t2] = packh2(h0, h1);
        Xl[(size_t)c * (Tn / 2) + t2] =
            packh2(__float2half_rn(v.x - __half2float(h0)),
                   __float2half_rn(v.y - __half2float(h1)));
        tile[2 * t2][c] = h0;
        tile[2 * t2 + 1][c] = h1;
    }
    __syncthreads();
    uint32_t* Xt = g_xth32 + ((size_t)b * Tn + t0) * (Cn / 2) + c0 / 2;
    const int tl = tid >> 4, c2 = tid & 15;
#pragma unroll
    for (int i = 0; i < 4; i++) {
        int t = tl + 16 * i;
        Xt[(size_t)t * (Cn / 2) + c2] = packh2(tile[t][2 * c2], tile[t][2 * c2 + 1]);
    }
}

// ---------------------------------------------------------------------------
// GEMM1 (symmetry trick): per tile compute S = Ah*Bh^T and M = Al*Bh^T only.
// E(i,j) = S(i,j) + M(i,j) + M(j,i) is assembled by softmax.
// CTA 128x128, 16 warps (32x32 tiles), BK=64, 3-stage cp.async.
// Stage words: AH 0, AL 4096, BH 8192; stride 12288 (144 KB total).
// ---------------------------------------------------------------------------
__device__ __forceinline__ void g1_chunk(uint32_t sbase, float accS[8][4],
                                         float accM[8][4], int warpM, int warpN,
                                         int lane) {
    const uint32_t AH = sbase, AL = sbase + 4096 * 4, BH = sbase + 8192 * 4;
#pragma unroll
    for (int ks = 0; ks < 4; ks++) {
        uint32_t ah[2][4], al[2][4], bh[4][2];
#pragma unroll
        for (int ma = 0; ma < 2; ma++) lda_frag(ah[ma], AH, warpM + ma * 16, ks, lane);
#pragma unroll
        for (int ma = 0; ma < 2; ma++) lda_frag(al[ma], AL, warpM + ma * 16, ks, lane);
        ldb_frag(&bh[0][0], BH, warpN, ks, lane);
        ldb_frag(&bh[2][0], BH, warpN + 16, ks, lane);
#pragma unroll
        for (int ma = 0; ma < 2; ma++)
#pragma unroll
            for (int na = 0; na < 4; na++) {
                mma_f16(accS[ma * 4 + na], ah[ma], bh[na]);
                mma_f16(accM[ma * 4 + na], al[ma], bh[na]);
            }
    }
}

__global__ __launch_bounds__(512, 1) void gemm1_h() {
    extern __shared__ uint32_t sm[];
    const uint32_t sb = smem_u32(sm);
    const int tid = threadIdx.x, lane = tid & 31, wid = tid >> 5;
    const int gid = lane >> 2, tig = lane & 3;
    const int warpM = (wid >> 2) * 32, warpN = (wid & 3) * 32;
    const size_t pa = ((size_t)blockIdx.z * Cn + blockIdx.y * 128) * (Tn / 2);
    const size_t pb = ((size_t)blockIdx.z * Cn + blockIdx.x * 128) * (Tn / 2);
    const uint32_t* Ahp = g_xh32 + pa;
    const uint32_t* Alp = g_xl32 + pa;
    const uint32_t* Bhp = g_xh32 + pb;

    float accS[8][4], accM[8][4];
#pragma unroll
    for (int a = 0; a < 8; a++)
#pragma unroll
        for (int c = 0; c < 4; c++) { accS[a][c] = 0.f; accM[a][c] = 0.f; }

    auto issue = [&](int c, int s) {
        uint32_t st = sb + s * 12288 * 4;
#pragma unroll
        for (int it = 0; it < 2; it++) {
            int idx = it * 512 + tid, row = idx >> 3, g = idx & 7;
            int w4 = 4 * woff(row, g);
            size_t go = (size_t)row * (Tn / 2) + c * 32 + g * 4;
            cp16(st + w4, Ahp + go);
            cp16(st + 4096 * 4 + w4, Alp + go);
            cp16(st + 8192 * 4 + w4, Bhp + go);
        }
    };

    issue(0, 0); CP_COMMIT();
    issue(1, 1); CP_COMMIT();
    issue(2, 2); CP_COMMIT();
    CP_WAIT(2);
    __syncthreads();

    const int NC = Tn / 64;   // 64
#pragma unroll 1
    for (int c = 0; c < NC; c++) {
        g1_chunk(sb + (c % 3) * 12288 * 4, accS, accM, warpM, warpN, lane);
        if (c + 1 < NC) {
            __syncthreads();
            if (c + 3 < NC) issue(c + 3, c % 3);
            CP_COMMIT();
            CP_WAIT(2);
            __syncthreads();
        }
    }

    float* P = (float*)g_e4 + (size_t)blockIdx.z * Cn * Cn;
    float* Mm = (float*)g_m4 + (size_t)blockIdx.z * Cn * Cn;
#pragma unroll
    for (int ma = 0; ma < 2; ma++)
#pragma unroll
        for (int na = 0; na < 4; na++) {
            const float* s = accS[ma * 4 + na];
            const float* m = accM[ma * 4 + na];
            int r0 = blockIdx.y * 128 + warpM + ma * 16 + gid;
            int cc = blockIdx.x * 128 + warpN + na * 8 + 2 * tig;
            size_t o0 = (size_t)r0 * Cn + cc, o1 = (size_t)(r0 + 8) * Cn + cc;
            *(float2*)(P + o0) = make_float2(s[0] + m[0], s[1] + m[1]);
            *(float2*)(P + o1) = make_float2(s[2] + m[2], s[3] + m[3]);
            *(float2*)(Mm + o0) = make_float2(m[0], m[1]);
            *(float2*)(Mm + o1) = make_float2(m[2], m[3]);
        }
}

// ---------------------------------------------------------------------------
// Softmax: E(i,j) = P(i,j) + M(j,i); w = exp(min_e - e)/sum; writes f16 h+l.
// ---------------------------------------------------------------------------
__global__ __launch_bounds__(256) void softmax_kernel() {
    const int row = blockIdx.x;               // b*Cn + i
    const int tid = threadIdx.x;
    const int i = row & (Cn - 1);
    const float* P = (float*)g_e4;
    const float* Mm = (float*)g_m4;

    float e = P[(size_t)row * Cn + tid] +
              Mm[((size_t)(row - i) + tid) * Cn + i];   // M(j=tid, i), batch base
    float v = e;
#pragma unroll
    for (int o = 16; o; o >>= 1) v = fminf(v, __shfl_xor_sync(0xffffffffu, v, o));
    __shared__ float red[8];
    __shared__ float bc[2];
    if ((tid & 31) == 0) red[tid >> 5] = v;
    __syncthreads();
    if (tid == 0) {
        float m = red[0];
#pragma unroll
        for (int k = 1; k < 8; k++) m = fminf(m, red[k]);
        bc[0] = m;
    }
    __syncthreads();
    float p = expf(bc[0] - e);
    v = p;
#pragma unroll
    for (int o = 16; o; o >>= 1) v += __shfl_xor_sync(0xffffffffu, v, o);
    if ((tid & 31) == 0) red[tid >> 5] = v;
    __syncthreads();
    if (tid == 0) {
        float s = 0.f;
#pragma unroll
        for (int k = 0; k < 8; k++) s += red[k];
        bc[1] = 1.0f / s;
    }
    __syncthreads();
    float w = p * bc[1];
    __half h = __float2half_rn(w);
    ((__half*)g_ah32)[(size_t)row * Cn + tid] = h;
    ((__half*)g_al32)[(size_t)row * Cn + tid] =
        __float2half_rn(w - __half2float(h));
}

// ---------------------------------------------------------------------------
// GEMM2: out = gamma*(Attn*X) + X. CTA 128x128, 8 warps (32x64 tiles), BK=64,
// 2-stage cp.async, __launch_bounds__(256,2) -> 2 CTAs/SM (overlap fill/epi).
// Stage words: AH 0, AL 4096, BH 8192; stride 12288 (96 KB total).
// ---------------------------------------------------------------------------
__device__ __forceinline__ void g2_chunk(uint32_t sbase, float acc[16][4],
                                         int warpM, int warpN, int lane) {
    const uint32_t AH = sbase, AL = sbase + 4096 * 4, BH = sbase + 8192 * 4;
#pragma unroll
    for (int ks = 0; ks < 4; ks++) {
        uint32_t ah[2][4], al[2][4], bh[8][2];
#pragma unroll
        for (int ma = 0; ma < 2; ma++) lda_frag(ah[ma], AH, warpM + ma * 16, ks, lane);
#pragma unroll
        for (int ma = 0; ma < 2; ma++) lda_frag(al[ma], AL, warpM + ma * 16, ks, lane);
#pragma unroll
        for (int p = 0; p < 4; p++) ldb_frag(&bh[2 * p][0], BH, warpN + p * 16, ks, lane);
#pragma unroll
        for (int ma = 0; ma < 2; ma++)
#pragma unroll
            for (int na = 0; na < 8; na++) {
                float* d = acc[ma * 8 + na];
                mma_f16(d, ah[ma], bh[na]);
                mma_f16(d, al[ma], bh[na]);
            }
    }
}

__global__ __launch_bounds__(256, 2) void gemm2_h(const float* __restrict__ x,
                                                  const float* __restrict__ gamma,
                                                  float* __restrict__ out) {
    extern __shared__ uint32_t sm[];
    const uint32_t sb = smem_u32(sm);
    const int tid = threadIdx.x, lane = tid & 31, wid = tid >> 5;
    const int gid = lane >> 2, tig = lane & 3;
    const int warpM = (wid >> 1) * 32, warpN = (wid & 1) * 64;
    const int bz = blockIdx.z, by = blockIdx.y, t0 = blockIdx.x * 128;

    const uint32_t* Ah = g_ah32 + ((size_t)bz * Cn + by * 128) * 128;
    const uint32_t* Al = g_al32 + ((size_t)bz * Cn + by * 128) * 128;
    const uint32_t* Bh = g_xth32 + ((size_t)bz * Tn + t0) * 128;

    float acc[16][4];
#pragma unroll
    for (int a = 0; a < 16; a++)
#pragma unroll
        for (int c = 0; c < 4; c++) acc[a][c] = 0.f;

    auto issue = [&](int c, int s) {
        uint32_t st = sb + s * 12288 * 4;
#pragma unroll
        for (int it = 0; it < 4; it++) {
            int idx = it * 256 + tid, row = idx >> 3, g = idx & 7;
            int w4 = 4 * woff(row, g);
            cp16(st + w4, Ah + (size_t)row * 128 + c * 32 + g * 4);
            cp16(st + 4096 * 4 + w4, Al + (size_t)row * 128 + c * 32 + g * 4);
            cp16(st + 8192 * 4 + w4, Bh + (size_t)row * 128 + c * 32 + g * 4);
        }
    };

    issue(0, 0); CP_COMMIT();
    issue(1, 1); CP_COMMIT();
    CP_WAIT(1);
    __syncthreads();

    const int NC = Cn / 64;   // 4
#pragma unroll 1
    for (int c = 0; c < NC; c++) {
        const int s = c & 1;
        g2_chunk(sb + s * 12288 * 4, acc, warpM, warpN, lane);
        if (c + 1 < NC) {
            __syncthreads();
            if (c + 2 < NC) {
                issue(c + 2, s); CP_COMMIT();
                CP_WAIT(1);
            } else {
                CP_WAIT(0);
            }
            __syncthreads();
        }
    }

    const float gm = __ldg(gamma);
    const float* Xb = x + (size_t)bz * Cn * Tn;
    float* Ob = out + (size_t)bz * Cn * Tn;
#pragma unroll
    for (int ma = 0; ma < 2; ma++)
#pragma unroll
        for (int na = 0; na < 8; na++) {
            const float* d = acc[ma * 8 + na];
            int r0 = by * 128 + warpM + ma * 16 + gid;
            int cc = t0 + warpN + na * 8 + 2 * tig;
            size_t o0 = (size_t)r0 * Tn + cc;
            size_t o1 = (size_t)(r0 + 8) * Tn + cc;
            float2 x0 = *(const float2*)(Xb + o0);
            float2 x1 = *(const float2*)(Xb + o1);
            *(float2*)(Ob + o0) = make_float2(gm * d[0] + x0.x, gm * d[1] + x0.y);
            *(float2*)(Ob + o1) = make_float2(gm * d[2] + x1.x, gm * d[3] + x1.y);
        }
}

// ---------------------------------------------------------------------------
extern "C" void kernel_launch(void* const* d_in, const int* in_sizes, int n_in,
                              void* d_out, int out_size) {
    (void)in_sizes; (void)n_in; (void)out_size;
    const float* x = (const float*)d_in[0];
    const float* gamma = (const float*)d_in[1];
    float* out = (float*)d_out;

    const int smem1 = 3 * 12288 * 4;   // 144 KB
    const int smem2 = 2 * 12288 * 4;   //  96 KB (x2 CTAs/SM = 192 KB)
    cudaFuncSetAttribute(gemm1_h, cudaFuncAttributeMaxDynamicSharedMemorySize, smem1);
    cudaFuncSetAttribute(gemm2_h, cudaFuncAttributeMaxDynamicSharedMemorySize, smem2);

    split_pre<<<dim3(Tn / 64, Cn / 32, Bn), 256>>>(x);
    gemm1_h<<<dim3(Cn / 128, Cn / 128, Bn), 512, smem1>>>();
    softmax_kernel<<<Bn * Cn, 256>>>();
    gemm2_h<<<dim3(Tn / 128, Cn / 128, Bn), 256, smem2>>>(x, gamma, out);
}

// round 14
// speedup vs baseline: 2.3633x; 1.0776x over previous
#include <cuda_runtime.h>
#include <cuda_fp16.h>
#include <cstdint>

#define Bn 32
#define Cn 256
#define Tn 4096

// Static device scratch (allocation-guard legal).
__device__ float4   g_e4[(size_t)Bn * Cn * Cn / 4];      //  8 MB P = S + M (fp32)
__device__ float4   g_m4[(size_t)Bn * Cn * Cn / 4];      //  8 MB M = Xl*Xh^T (fp32)
__device__ uint32_t g_ah32[(size_t)Bn * Cn * Cn / 2];    //  4 MB attn hi (f16)
__device__ uint32_t g_xh32[(size_t)Bn * Cn * Tn / 2];    // 67 MB X hi  row-major
__device__ uint32_t g_xl32[(size_t)Bn * Cn * Tn / 2];    // 67 MB X lo  row-major
__device__ uint32_t g_xth32[(size_t)Bn * Tn * Cn / 2];   // 67 MB X^T hi

// ---------------------------------------------------------------------------
// Tile layout (proven): row = 64 k f16 = 128 B = 32 words; 16B group g at
// word offset row*32 + (g^(row&7))*4. cp.async / LDSM conflict-free.
// ---------------------------------------------------------------------------
__device__ __forceinline__ int woff(int row, int g) {
    return row * 32 + ((g ^ (row & 7)) << 2);
}
__device__ __forceinline__ uint32_t smem_u32(const void* p) {
    uint32_t a;
    asm("{ .reg .u64 t; cvta.to.shared.u64 t, %1; cvt.u32.u64 %0, t; }"
        : "=r"(a) : "l"(p));
    return a;
}
__device__ __forceinline__ uint32_t packh2(__half a, __half b) {
    return (uint32_t)__half_as_ushort(a) | ((uint32_t)__half_as_ushort(b) << 16);
}
__device__ __forceinline__ void mma_f16(float* d, const uint32_t* a, const uint32_t* b) {
    asm volatile(
        "mma.sync.aligned.m16n8k16.row.col.f32.f16.f16.f32 "
        "{%0,%1,%2,%3}, {%4,%5,%6,%7}, {%8,%9}, {%0,%1,%2,%3};"
        : "+f"(d[0]), "+f"(d[1]), "+f"(d[2]), "+f"(d[3])
        : "r"(a[0]), "r"(a[1]), "r"(a[2]), "r"(a[3]), "r"(b[0]), "r"(b[1]));
}
__device__ __forceinline__ void ldsm4(uint32_t& r0, uint32_t& r1, uint32_t& r2,
                                      uint32_t& r3, uint32_t addr) {
    asm volatile("ldmatrix.sync.aligned.m8n8.x4.shared.b16 {%0,%1,%2,%3}, [%4];"
                 : "=r"(r0), "=r"(r1), "=r"(r2), "=r"(r3) : "r"(addr));
}
__device__ __forceinline__ void lda_frag(uint32_t* a, uint32_t tb, int mrow,
                                         int ks, int lane) {
    int oct = lane >> 3, l7 = lane & 7;
    int row = mrow + ((oct & 1) << 3) + l7;
    int g = 2 * ks + (oct >> 1);
    ldsm4(a[0], a[1], a[2], a[3], tb + 4 * woff(row, g));
}
__device__ __forceinline__ void ldb_frag(uint32_t* b, uint32_t tb, int nrow,
                                         int ks, int lane) {
    int oct = lane >> 3, l7 = lane & 7;
    int row = nrow + ((oct >> 1) << 3) + l7;
    int g = 2 * ks + (oct & 1);
    ldsm4(b[0], b[1], b[2], b[3], tb + 4 * woff(row, g));
}
__device__ __forceinline__ void cp16(uint32_t saddr, const void* g) {
    asm volatile("cp.async.cg.shared.global [%0], [%1], 16;" :: "r"(saddr), "l"(g));
}
#define CP_COMMIT() asm volatile("cp.async.commit_group;" ::: "memory")
#define CP_WAIT(N)  asm volatile("cp.async.wait_group %0;" :: "n"(N) : "memory")

// ---------------------------------------------------------------------------
// Prepass: one read of X -> Xh (rm), Xl (rm), Xth (transposed hi), all f16.
// ---------------------------------------------------------------------------
__global__ __launch_bounds__(256) void split_pre(const float* __restrict__ x) {
    __shared__ __half tile[64][34];
    const int b = blockIdx.z, c0 = blockIdx.y * 32, t0 = blockIdx.x * 64;
    const int tid = threadIdx.x, cl = tid >> 5, t2 = tid & 31;
    const float* Xb = x + ((size_t)b * Cn + c0) * Tn + t0;
    uint32_t* Xh = g_xh32 + ((size_t)b * Cn + c0) * (Tn / 2) + t0 / 2;
    uint32_t* Xl = g_xl32 + ((size_t)b * Cn + c0) * (Tn / 2) + t0 / 2;
#pragma unroll
    for (int i = 0; i < 4; i++) {
        int c = cl + 8 * i;
        float2 v = *(const float2*)(Xb + (size_t)c * Tn + 2 * t2);
        __half h0 = __float2half_rn(v.x), h1 = __float2half_rn(v.y);
        Xh[(size_t)c * (Tn / 2) + t2] = packh2(h0, h1);
        Xl[(size_t)c * (Tn / 2) + t2] =
            packh2(__float2half_rn(v.x - __half2float(h0)),
                   __float2half_rn(v.y - __half2float(h1)));
        tile[2 * t2][c] = h0;
        tile[2 * t2 + 1][c] = h1;
    }
    __syncthreads();
    uint32_t* Xt = g_xth32 + ((size_t)b * Tn + t0) * (Cn / 2) + c0 / 2;
    const int tl = tid >> 4, c2 = tid & 15;
#pragma unroll
    for (int i = 0; i < 4; i++) {
        int t = tl + 16 * i;
        Xt[(size_t)t * (Cn / 2) + c2] = packh2(tile[t][2 * c2], tile[t][2 * c2 + 1]);
    }
}

// ---------------------------------------------------------------------------
// GEMM1 (symmetry trick): per tile compute S = Ah*Bh^T and M = Al*Bh^T only.
// E(i,j) = S(i,j) + M(i,j) + M(j,i) is assembled by softmax.
// CTA 128x128, 16 warps (32x32 tiles), BK=64, 3-stage cp.async.
// Stage words: AH 0, AL 4096, BH 8192; stride 12288 (144 KB total).
// ---------------------------------------------------------------------------
__device__ __forceinline__ void g1_chunk(uint32_t sbase, float accS[8][4],
                                         float accM[8][4], int warpM, int warpN,
                                         int lane) {
    const uint32_t AH = sbase, AL = sbase + 4096 * 4, BH = sbase + 8192 * 4;
#pragma unroll
    for (int ks = 0; ks < 4; ks++) {
        uint32_t ah[2][4], al[2][4], bh[4][2];
#pragma unroll
        for (int ma = 0; ma < 2; ma++) lda_frag(ah[ma], AH, warpM + ma * 16, ks, lane);
#pragma unroll
        for (int ma = 0; ma < 2; ma++) lda_frag(al[ma], AL, warpM + ma * 16, ks, lane);
        ldb_frag(&bh[0][0], BH, warpN, ks, lane);
        ldb_frag(&bh[2][0], BH, warpN + 16, ks, lane);
#pragma unroll
        for (int ma = 0; ma < 2; ma++)
#pragma unroll
            for (int na = 0; na < 4; na++) {
                mma_f16(accS[ma * 4 + na], ah[ma], bh[na]);
                mma_f16(accM[ma * 4 + na], al[ma], bh[na]);
            }
    }
}

__global__ __launch_bounds__(512, 1) void gemm1_h() {
    extern __shared__ uint32_t sm[];
    const uint32_t sb = smem_u32(sm);
    const int tid = threadIdx.x, lane = tid & 31, wid = tid >> 5;
    const int gid = lane >> 2, tig = lane & 3;
    const int warpM = (wid >> 2) * 32, warpN = (wid & 3) * 32;
    const size_t pa = ((size_t)blockIdx.z * Cn + blockIdx.y * 128) * (Tn / 2);
    const size_t pb = ((size_t)blockIdx.z * Cn + blockIdx.x * 128) * (Tn / 2);
    const uint32_t* Ahp = g_xh32 + pa;
    const uint32_t* Alp = g_xl32 + pa;
    const uint32_t* Bhp = g_xh32 + pb;

    float accS[8][4], accM[8][4];
#pragma unroll
    for (int a = 0; a < 8; a++)
#pragma unroll
        for (int c = 0; c < 4; c++) { accS[a][c] = 0.f; accM[a][c] = 0.f; }

    auto issue = [&](int c, int s) {
        uint32_t st = sb + s * 12288 * 4;
#pragma unroll
        for (int it = 0; it < 2; it++) {
            int idx = it * 512 + tid, row = idx >> 3, g = idx & 7;
            int w4 = 4 * woff(row, g);
            size_t go = (size_t)row * (Tn / 2) + c * 32 + g * 4;
            cp16(st + w4, Ahp + go);
            cp16(st + 4096 * 4 + w4, Alp + go);
            cp16(st + 8192 * 4 + w4, Bhp + go);
        }
    };

    issue(0, 0); CP_COMMIT();
    issue(1, 1); CP_COMMIT();
    issue(2, 2); CP_COMMIT();
    CP_WAIT(2);
    __syncthreads();

    const int NC = Tn / 64;   // 64
#pragma unroll 1
    for (int c = 0; c < NC; c++) {
        g1_chunk(sb + (c % 3) * 12288 * 4, accS, accM, warpM, warpN, lane);
        if (c + 1 < NC) {
            __syncthreads();
            if (c + 3 < NC) issue(c + 3, c % 3);
            CP_COMMIT();
            CP_WAIT(2);
            __syncthreads();
        }
    }

    float* P = (float*)g_e4 + (size_t)blockIdx.z * Cn * Cn;
    float* Mm = (float*)g_m4 + (size_t)blockIdx.z * Cn * Cn;
#pragma unroll
    for (int ma = 0; ma < 2; ma++)
#pragma unroll
        for (int na = 0; na < 4; na++) {
            const float* s = accS[ma * 4 + na];
            const float* m = accM[ma * 4 + na];
            int r0 = blockIdx.y * 128 + warpM + ma * 16 + gid;
            int cc = blockIdx.x * 128 + warpN + na * 8 + 2 * tig;
            size_t o0 = (size_t)r0 * Cn + cc, o1 = (size_t)(r0 + 8) * Cn + cc;
            *(float2*)(P + o0) = make_float2(s[0] + m[0], s[1] + m[1]);
            *(float2*)(P + o1) = make_float2(s[2] + m[2], s[3] + m[3]);
            *(float2*)(Mm + o0) = make_float2(m[0], m[1]);
            *(float2*)(Mm + o1) = make_float2(m[2], m[3]);
        }
}

// ---------------------------------------------------------------------------
// Softmax: E(i,j) = P(i,j) + M(j,i); w = exp(min_e - e)/sum; writes f16 hi.
// ---------------------------------------------------------------------------
__global__ __launch_bounds__(256) void softmax_kernel() {
    const int row = blockIdx.x;               // b*Cn + i
    const int tid = threadIdx.x;
    const int i = row & (Cn - 1);
    const float* P = (float*)g_e4;
    const float* Mm = (float*)g_m4;

    float e = P[(size_t)row * Cn + tid] +
              Mm[((size_t)(row - i) + tid) * Cn + i];   // M(j=tid, i), batch base
    float v = e;
#pragma unroll
    for (int o = 16; o; o >>= 1) v = fminf(v, __shfl_xor_sync(0xffffffffu, v, o));
    __shared__ float red[8];
    __shared__ float bc[2];
    if ((tid & 31) == 0) red[tid >> 5] = v;
    __syncthreads();
    if (tid == 0) {
        float m = red[0];
#pragma unroll
        for (int k = 1; k < 8; k++) m = fminf(m, red[k]);
        bc[0] = m;
    }
    __syncthreads();
    float p = expf(bc[0] - e);
    v = p;
#pragma unroll
    for (int o = 16; o; o >>= 1) v += __shfl_xor_sync(0xffffffffu, v, o);
    if ((tid & 31) == 0) red[tid >> 5] = v;
    __syncthreads();
    if (tid == 0) {
        float s = 0.f;
#pragma unroll
        for (int k = 0; k < 8; k++) s += red[k];
        bc[1] = 1.0f / s;
    }
    __syncthreads();
    ((__half*)g_ah32)[(size_t)row * Cn + tid] = __float2half_rn(p * bc[1]);
}

// ---------------------------------------------------------------------------
// GEMM2 (single-product A): out = gamma*(Attn_h*X_h) + X. CTA 128x128,
// 8 warps (32x64 tiles), BK=64, 3-stage cp.async, 2 CTAs/SM.
// Stage words: AH 0, BH 4096; stride 8192 (96 KB total x 2 CTAs = 192 KB).
// ---------------------------------------------------------------------------
__device__ __forceinline__ void g2_chunk(uint32_t sbase, float acc[16][4],
                                         int warpM, int warpN, int lane) {
    const uint32_t AH = sbase, BH = sbase + 4096 * 4;
#pragma unroll
    for (int ks = 0; ks < 4; ks++) {
        uint32_t ah[2][4], bh[8][2];
#pragma unroll
        for (int ma = 0; ma < 2; ma++) lda_frag(ah[ma], AH, warpM + ma * 16, ks, lane);
#pragma unroll
        for (int p = 0; p < 4; p++) ldb_frag(&bh[2 * p][0], BH, warpN + p * 16, ks, lane);
#pragma unroll
        for (int ma = 0; ma < 2; ma++)
#pragma unroll
            for (int na = 0; na < 8; na++)
                mma_f16(acc[ma * 8 + na], ah[ma], bh[na]);
    }
}

__global__ __launch_bounds__(256, 2) void gemm2_h(const float* __restrict__ x,
                                                  const float* __restrict__ gamma,
                                                  float* __restrict__ out) {
    extern __shared__ uint32_t sm[];
    const uint32_t sb = smem_u32(sm);
    const int tid = threadIdx.x, lane = tid & 31, wid = tid >> 5;
    const int gid = lane >> 2, tig = lane & 3;
    const int warpM = (wid >> 1) * 32, warpN = (wid & 1) * 64;
    const int bz = blockIdx.z, by = blockIdx.y, t0 = blockIdx.x * 128;

    const uint32_t* Ah = g_ah32 + ((size_t)bz * Cn + by * 128) * 128;
    const uint32_t* Bh = g_xth32 + ((size_t)bz * Tn + t0) * 128;

    float acc[16][4];
#pragma unroll
    for (int a = 0; a < 16; a++)
#pragma unroll
        for (int c = 0; c < 4; c++) acc[a][c] = 0.f;

    auto issue = [&](int c, int s) {
        uint32_t st = sb + s * 8192 * 4;
#pragma unroll
        for (int it = 0; it < 4; it++) {
            int idx = it * 256 + tid, row = idx >> 3, g = idx & 7;
            int w4 = 4 * woff(row, g);
            cp16(st + w4, Ah + (size_t)row * 128 + c * 32 + g * 4);
            cp16(st + 4096 * 4 + w4, Bh + (size_t)row * 128 + c * 32 + g * 4);
        }
    };

    issue(0, 0); CP_COMMIT();
    issue(1, 1); CP_COMMIT();
    issue(2, 2); CP_COMMIT();
    CP_WAIT(2);
    __syncthreads();

    const int NC = Cn / 64;   // 4
#pragma unroll 1
    for (int c = 0; c < NC; c++) {
        g2_chunk(sb + (c % 3) * 8192 * 4, acc, warpM, warpN, lane);
        if (c + 1 < NC) {
            __syncthreads();
            if (c + 3 < NC) issue(c + 3, c % 3);
            CP_COMMIT();
            CP_WAIT(2);
            __syncthreads();
        }
    }

    const float gm = __ldg(gamma);
    const float* Xb = x + (size_t)bz * Cn * Tn;
    float* Ob = out + (size_t)bz * Cn * Tn;
#pragma unroll
    for (int ma = 0; ma < 2; ma++)
#pragma unroll
        for (int na = 0; na < 8; na++) {
            const float* d = acc[ma * 8 + na];
            int r0 = by * 128 + warpM + ma * 16 + gid;
            int cc = t0 + warpN + na * 8 + 2 * tig;
            size_t o0 = (size_t)r0 * Tn + cc;
            size_t o1 = (size_t)(r0 + 8) * Tn + cc;
            float2 x0 = *(const float2*)(Xb + o0);
            float2 x1 = *(const float2*)(Xb + o1);
            *(float2*)(Ob + o0) = make_float2(gm * d[0] + x0.x, gm * d[1] + x0.y);
            *(float2*)(Ob + o1) = make_float2(gm * d[2] + x1.x, gm * d[3] + x1.y);
        }
}

// ---------------------------------------------------------------------------
extern "C" void kernel_launch(void* const* d_in, const int* in_sizes, int n_in,
                              void* d_out, int out_size) {
    (void)in_sizes; (void)n_in; (void)out_size;
    const float* x = (const float*)d_in[0];
    const float* gamma = (const float*)d_in[1];
    float* out = (float*)d_out;

    const int smem1 = 3 * 12288 * 4;   // 144 KB
    const int smem2 = 3 * 8192 * 4;    //  96 KB (x2 CTAs/SM = 192 KB)
    cudaFuncSetAttribute(gemm1_h, cudaFuncAttributeMaxDynamicSharedMemorySize, smem1);
    cudaFuncSetAttribute(gemm2_h, cudaFuncAttributeMaxDynamicSharedMemorySize, smem2);

    split_pre<<<dim3(Tn / 64, Cn / 32, Bn), 256>>>(x);
    gemm1_h<<<dim3(Cn / 128, Cn / 128, Bn), 512, smem1>>>();
    softmax_kernel<<<Bn * Cn, 256>>>();
    gemm2_h<<<dim3(Tn / 128, Cn / 128, Bn), 256, smem2>>>(x, gamma, out);
}